// round 14
// baseline (speedup 1.0000x reference)
#include <cuda_runtime.h>
#include <cuda_fp16.h>
#include <cstdint>

#define BS   16384
#define EPSV 1e-5f

// ---------------------------------------------------------------------------
// Device scratch (no allocs allowed)
// ---------------------------------------------------------------------------
__device__ __half g_a1[(size_t)BS * 1024];   // [b][k] : q1_0 | x   (fp16)
__device__ __half g_a2[(size_t)BS * 2048];   // [b][k] : q2_0 | h1  (fp16)
__device__ __half g_w1[1024 * 1024];         // [n][k] de-interleaved
__device__ __half g_w2[512 * 3072];          // [n][k] w2|wsk combined
__device__ int    g_tile;                    // global tile counter
__device__ int    g_rowcnt[128];             // gemm1 completions per M-row-block

// ---------------------------------------------------------------------------
// Helpers
// ---------------------------------------------------------------------------
__device__ __forceinline__ uint32_t s2u(const void* p) {
    uint32_t a;
    asm("{ .reg .u64 t; cvta.to.shared.u64 t, %1; cvt.u32.u64 %0, t; }"
        : "=r"(a) : "l"(p));
    return a;
}
__device__ __forceinline__ void cp16(uint32_t saddr, const void* gptr) {
    asm volatile("cp.async.cg.shared.global [%0], [%1], 16;"
                 :: "r"(saddr), "l"(__cvta_generic_to_global(gptr)) : "memory");
}
#define CP_COMMIT() asm volatile("cp.async.commit_group;" ::: "memory")
#define CP_WAIT(n)  asm volatile("cp.async.wait_group %0;" :: "n"(n) : "memory")

__device__ __forceinline__ void ldmx4(uint32_t* r, uint32_t addr) {
    asm volatile("ldmatrix.sync.aligned.m8n8.x4.shared.b16 {%0,%1,%2,%3}, [%4];"
                 : "=r"(r[0]), "=r"(r[1]), "=r"(r[2]), "=r"(r[3]) : "r"(addr));
}
__device__ __forceinline__ void mma16816(float* d, const uint32_t* a,
                                         uint32_t b0, uint32_t b1) {
    asm volatile(
        "mma.sync.aligned.m16n8k16.row.col.f32.f16.f16.f32 "
        "{%0,%1,%2,%3}, {%4,%5,%6,%7}, {%8,%9}, {%0,%1,%2,%3};"
        : "+f"(d[0]), "+f"(d[1]), "+f"(d[2]), "+f"(d[3])
        : "r"(a[0]), "r"(a[1]), "r"(a[2]), "r"(a[3]), "r"(b0), "r"(b1));
}
__device__ __forceinline__ uint32_t pk2h(__half a, __half b) {
    __half2 t(a, b);
    return *reinterpret_cast<uint32_t*>(&t);
}
__device__ __forceinline__ int ld_acq(const int* p) {
    int v;
    asm volatile("ld.acquire.gpu.global.b32 %0, [%1];"
                 : "=r"(v) : "l"(p) : "memory");
    return v;
}

// ---------------------------------------------------------------------------
// Merged prep kernel: a1 conv | a2 conv | w1 prep | w2 prep  (+ counter reset)
// Wide ephemeral grid — memory-bound work needs maximal thread parallelism.
// ---------------------------------------------------------------------------
__global__ void prep_kernel(const float* __restrict__ q1, const float* __restrict__ x,
                            const float* __restrict__ q2,
                            const float* __restrict__ w1,
                            const float* __restrict__ w2, const float* __restrict__ wsk)
{
    const int bid = blockIdx.x;
    const int tid = threadIdx.x;
    if (bid == 0) {                               // reset scheduler state
        if (tid < 128) g_rowcnt[tid] = 0;
        if (tid == 128) g_tile = 0;
    }
    if (bid < 16384) {                            // a1: q1_0 | x  -> fp16
        int idx = bid * 256 + tid;
        int b = idx >> 8;
        int k4 = (idx & 255) << 2;
        const float* src = (k4 < 512) ? (q1 + (size_t)b * 512 + k4)
                                      : (x  + (size_t)b * 512 + k4 - 512);
        float4 v = *(const float4*)src;
        size_t o = (size_t)b * 1024 + k4;
        *(uint2*)(g_a1 + o) = make_uint2(pk2h(__float2half_rn(v.x), __float2half_rn(v.y)),
                                         pk2h(__float2half_rn(v.z), __float2half_rn(v.w)));
    } else if (bid < 32768) {                     // a2 cols 0..1023: q2_0 -> fp16
        int idx = (bid - 16384) * 256 + tid;
        int b = idx >> 8;
        int k4 = (idx & 255) << 2;
        float4 v = *(const float4*)(q2 + (size_t)b * 1024 + k4);
        size_t o = (size_t)b * 2048 + k4;
        *(uint2*)(g_a2 + o) = make_uint2(pk2h(__float2half_rn(v.x), __float2half_rn(v.y)),
                                         pk2h(__float2half_rn(v.z), __float2half_rn(v.w)));
    } else if (bid < 36864) {                     // w1 de-interleave -> [n][k]
        int idx = (bid - 32768) * 256 + tid;
        int n = idx >> 10, k = idx & 1023;
        int src = (k < 512) ? (2 * k) : (2 * (k - 512) + 1);
        g_w1[idx] = __float2half_rn(w1[(size_t)n * 1024 + src]);
    } else {                                      // w2|wsk combined -> [n][k]
        int idx = (bid - 36864) * 256 + tid;
        int n = idx / 3072, k = idx - n * 3072;
        float v;
        if (k < 1024)      v = w2 [(size_t)n * 2048 + 2 * k];
        else if (k < 2048) v = w2 [(size_t)n * 2048 + 2 * (k - 1024) + 1];
        else if (k < 2560) v = wsk[(size_t)n * 1024 + 2 * (k - 2048)];
        else               v = wsk[(size_t)n * 1024 + 2 * (k - 2560) + 1];
        g_w2[idx] = __float2half_rn(v);
    }
}

// ---------------------------------------------------------------------------
// Fused persistent GEMM kernel.
// Tiles 0..1023  : gemm1 (bm = (t>>3)*128, bn = (t&7)*128), K=1024
// Tiles 1024..1535: gemm2 (bm = (u>>2)*128, bn = (u&3)*128), K=3072
// CTA 128x128, K-chunk 64, 2-stage double buffer.
// 128 threads = 4 warps in a 2x2 grid, warp tile 64x64 (acc = 128 regs).
// pitch 144 B, 2 CTAs/SM, 255-reg budget.
// ---------------------------------------------------------------------------
#define PITCH      144
#define B_OFF      (128 * PITCH)
#define STAGE_B    (2 * 128 * PITCH)      // 36864
#define PARAM_OFF  (2 * STAGE_B)          // 73728
#define SMEM_TOTAL (PARAM_OFF + 2048)

__global__ __launch_bounds__(128, 2)
void fused_kernel(const float* __restrict__ b1, const float* __restrict__ s1,
                  const float* __restrict__ bb1, const float* __restrict__ m1,
                  const float* __restrict__ v1,
                  const float* __restrict__ b2, const float* __restrict__ bsk,
                  const float* __restrict__ s2, const float* __restrict__ bb2,
                  const float* __restrict__ m2, const float* __restrict__ v2,
                  float* __restrict__ outp)
{
    extern __shared__ char smem[];
    const uint32_t sbase = s2u(smem);
    const int tid  = threadIdx.x;
    const int wid  = tid >> 5, lane = tid & 31;
    const int wm   = (wid & 1) * 64;      // warp M offset
    const int wn   = (wid >> 1) * 64;     // warp N offset

    float* scp = (float*)(smem + PARAM_OFF);
    float* bip = scp + 128;
    float* bcp = scp + 256;
    int*  tilep = (int*)(smem + PARAM_OFF + 1536);

    const int mrow = lane & 15, msel = lane >> 4;
    const uint32_t aoff = (wm + mrow) * PITCH + msel * 16;
    const uint32_t boff = (wn + mrow) * PITCH + msel * 16;
    const int g  = lane >> 2, tg = lane & 3;

    for (;;) {
        if (tid == 0) *tilep = atomicAdd(&g_tile, 1);
        __syncthreads();
        const int t = *tilep;
        if (t >= 1536) break;

        const bool g1 = (t < 1024);
        int bm, bn, NC;
        if (g1) { bm = (t >> 3) * 128;          bn = (t & 7) * 128; NC = 16; }
        else    { int u = t - 1024; bm = (u >> 2) * 128; bn = (u & 3) * 128; NC = 48; }
        const __half* Bw = g1 ? g_w1 : g_w2;
        const int bstr   = g1 ? 1024 : 3072;

        if (!g1) {                        // wait for h1 rows [bm, bm+128)
            if (tid == 0) {
                const int* cp = &g_rowcnt[bm >> 7];
                while (ld_acq(cp) < 8) __nanosleep(128);
            }
            __syncthreads();
        }

        float acc[4][8][4];
#pragma unroll
        for (int i = 0; i < 4; i++)
#pragma unroll
            for (int j = 0; j < 8; j++)
#pragma unroll
                for (int k = 0; k < 4; k++) acc[i][j][k] = 0.f;

        auto load_stage = [&](int slot, int c) {
            const int k0 = c * 64;
            const __half* Aa; int astr, acol;
            if (g1)             { Aa = g_a1; astr = 1024; acol = k0; }
            else if (k0 < 2048) { Aa = g_a2; astr = 2048; acol = k0; }
            else                { Aa = g_a1; astr = 1024; acol = k0 - 2048; }
            const uint32_t st = sbase + slot * STAGE_B;
#pragma unroll
            for (int j = 0; j < 8; j++) {
                int idx = j * 128 + tid;
                int row = idx >> 3, ch = idx & 7;
                cp16(st + row * PITCH + ch * 16,
                     Aa + (size_t)(bm + row) * astr + acol + ch * 8);
                cp16(st + B_OFF + row * PITCH + ch * 16,
                     Bw + (size_t)(bn + row) * bstr + k0 + ch * 8);
            }
        };

        load_stage(0, 0); CP_COMMIT();

        for (int c = 0; c < NC; c++) {
            CP_WAIT(0);
            __syncthreads();
            if (c + 1 < NC) { load_stage((c + 1) & 1, c + 1); CP_COMMIT(); }
            const uint32_t st = sbase + (c & 1) * STAGE_B;
#pragma unroll
            for (int ks = 0; ks < 4; ks++) {           // four k16 substeps
                const uint32_t kadd = ks * 32;
                uint32_t fb[4][4];
#pragma unroll
                for (int p = 0; p < 4; p++)
                    ldmx4(fb[p], st + B_OFF + boff + p * 16 * PITCH + kadd);
#pragma unroll
                for (int mt = 0; mt < 4; mt++) {
                    uint32_t fa[4];
                    ldmx4(fa, st + aoff + mt * 16 * PITCH + kadd);
#pragma unroll
                    for (int nt = 0; nt < 8; nt++) {
                        const int p = nt >> 1, o = nt & 1;
                        mma16816(acc[mt][nt], fa, fb[p][o], fb[p][2 + o]);
                    }
                }
            }
        }

        // ---- epilogue: stage per-column params, then write ----
        {
            const int n = bn + tid;
            float s, bi, bc;
            if (g1) { s = s1[n] * rsqrtf(v1[n] + EPSV); bi = bb1[n] - m1[n] * s; bc = b1[n]; }
            else    { s = s2[n] * rsqrtf(v2[n] + EPSV); bi = bb2[n] - m2[n] * s; bc = b2[n] + bsk[n]; }
            scp[tid] = s; bip[tid] = bi; bcp[tid] = bc;
        }
        __syncthreads();

#pragma unroll
        for (int mt = 0; mt < 4; mt++) {
#pragma unroll
            for (int nt = 0; nt < 8; nt++) {
                const int nl = wn + nt * 8 + 2 * tg;
                const float s0 = scp[nl], s1v = scp[nl + 1];
                const float i0 = bip[nl], i1 = bip[nl + 1];
                const float c0 = bcp[nl], c1 = bcp[nl + 1];
#pragma unroll
                for (int half = 0; half < 2; half++) {
                    const int m = bm + wm + mt * 16 + g + half * 8;
                    const float v0 = fmaxf(acc[mt][nt][2 * half]     + c0, 0.f) * s0  + i0;
                    const float v1e = fmaxf(acc[mt][nt][2 * half + 1] + c1, 0.f) * s1v + i1;
                    if (g1) {
                        const size_t o = (size_t)m * 2048 + 1024 + bn + nl;
                        *(uint32_t*)(g_a2 + o) = pk2h(__float2half_rn(v0), __float2half_rn(v1e));
                    } else {
                        *(float2*)(outp + (size_t)m * 512 + bn + nl) = make_float2(v0, v1e);
                    }
                }
            }
        }

        if (g1) {               // publish h1 row-block completion
            __threadfence();
            __syncthreads();
            if (tid == 0) atomicAdd(&g_rowcnt[bm >> 7], 1);
        }
    }
}

// ---------------------------------------------------------------------------
extern "C" void kernel_launch(void* const* d_in, const int* in_sizes, int n_in,
                              void* d_out, int out_size) {
    const float* x   = (const float*)d_in[0];
    const float* q1  = (const float*)d_in[1];
    const float* q2  = (const float*)d_in[2];
    const float* w1  = (const float*)d_in[3];
    const float* b1  = (const float*)d_in[4];
    const float* w2  = (const float*)d_in[5];
    const float* b2  = (const float*)d_in[6];
    const float* wsk = (const float*)d_in[7];
    const float* bsk = (const float*)d_in[8];
    const float* s1  = (const float*)d_in[9];
    const float* bb1 = (const float*)d_in[10];
    const float* m1  = (const float*)d_in[11];
    const float* v1  = (const float*)d_in[12];
    const float* s2  = (const float*)d_in[13];
    const float* bb2 = (const float*)d_in[14];
    const float* m2  = (const float*)d_in[15];
    const float* v2  = (const float*)d_in[16];
    float* out = (float*)d_out;

    cudaFuncSetAttribute(fused_kernel, cudaFuncAttributeMaxDynamicSharedMemorySize, SMEM_TOTAL);

    // 16384 (a1) + 16384 (a2) + 4096 (w1) + 6144 (w2) blocks
    prep_kernel<<<43008, 256>>>(q1, x, q2, w1, w2, wsk);
    fused_kernel<<<296, 128, SMEM_TOTAL>>>(b1, s1, bb1, m1, v1,
                                           b2, bsk, s2, bb2, m2, v2, out);
}

// round 15
// speedup vs baseline: 1.5000x; 1.5000x over previous
#include <cuda_runtime.h>
#include <cuda_fp16.h>
#include <cstdint>

#define BS   16384
#define EPSV 1e-5f

// ---------------------------------------------------------------------------
// Device scratch (no allocs allowed)
// ---------------------------------------------------------------------------
__device__ __half g_a1[(size_t)BS * 1024];   // [b][k] : q1_0 | x   (fp16)
__device__ __half g_a2[(size_t)BS * 2048];   // [b][k] : q2_0 | h1  (fp16)
__device__ __half g_w1[1024 * 1024];         // [n][k] de-interleaved
__device__ __half g_w2[512 * 3072];          // [n][k] w2|wsk combined
__device__ int    g_tile;                    // global tile counter
__device__ int    g_rowcnt[128];             // gemm1 completions per M-row-block

// ---------------------------------------------------------------------------
// Helpers
// ---------------------------------------------------------------------------
__device__ __forceinline__ uint32_t s2u(const void* p) {
    uint32_t a;
    asm("{ .reg .u64 t; cvta.to.shared.u64 t, %1; cvt.u32.u64 %0, t; }"
        : "=r"(a) : "l"(p));
    return a;
}
__device__ __forceinline__ void cp16(uint32_t saddr, const void* gptr) {
    asm volatile("cp.async.cg.shared.global [%0], [%1], 16;"
                 :: "r"(saddr), "l"(__cvta_generic_to_global(gptr)) : "memory");
}
#define CP_COMMIT() asm volatile("cp.async.commit_group;" ::: "memory")
#define CP_WAIT(n)  asm volatile("cp.async.wait_group %0;" :: "n"(n) : "memory")

__device__ __forceinline__ void ldmx4(uint32_t* r, uint32_t addr) {
    asm volatile("ldmatrix.sync.aligned.m8n8.x4.shared.b16 {%0,%1,%2,%3}, [%4];"
                 : "=r"(r[0]), "=r"(r[1]), "=r"(r[2]), "=r"(r[3]) : "r"(addr));
}
__device__ __forceinline__ void mma16816(float* d, const uint32_t* a,
                                         uint32_t b0, uint32_t b1) {
    asm volatile(
        "mma.sync.aligned.m16n8k16.row.col.f32.f16.f16.f32 "
        "{%0,%1,%2,%3}, {%4,%5,%6,%7}, {%8,%9}, {%0,%1,%2,%3};"
        : "+f"(d[0]), "+f"(d[1]), "+f"(d[2]), "+f"(d[3])
        : "r"(a[0]), "r"(a[1]), "r"(a[2]), "r"(a[3]), "r"(b0), "r"(b1));
}
__device__ __forceinline__ uint32_t pk2h(__half a, __half b) {
    __half2 t(a, b);
    return *reinterpret_cast<uint32_t*>(&t);
}
__device__ __forceinline__ int ld_acq(const int* p) {
    int v;
    asm volatile("ld.acquire.gpu.global.b32 %0, [%1];"
                 : "=r"(v) : "l"(p) : "memory");
    return v;
}

// ---------------------------------------------------------------------------
// Merged prep kernel: a1 conv | a2 conv | w1 prep | w2 prep  (+ counter reset)
// Wide ephemeral grid — memory-bound work needs maximal thread parallelism.
// ---------------------------------------------------------------------------
__global__ void prep_kernel(const float* __restrict__ q1, const float* __restrict__ x,
                            const float* __restrict__ q2,
                            const float* __restrict__ w1,
                            const float* __restrict__ w2, const float* __restrict__ wsk)
{
    const int bid = blockIdx.x;
    const int tid = threadIdx.x;
    if (bid == 0) {                               // reset scheduler state
        if (tid < 128) g_rowcnt[tid] = 0;
        if (tid == 128) g_tile = 0;
    }
    if (bid < 16384) {                            // a1: q1_0 | x  -> fp16
        int idx = bid * 256 + tid;
        int b = idx >> 8;
        int k4 = (idx & 255) << 2;
        const float* src = (k4 < 512) ? (q1 + (size_t)b * 512 + k4)
                                      : (x  + (size_t)b * 512 + k4 - 512);
        float4 v = *(const float4*)src;
        size_t o = (size_t)b * 1024 + k4;
        *(uint2*)(g_a1 + o) = make_uint2(pk2h(__float2half_rn(v.x), __float2half_rn(v.y)),
                                         pk2h(__float2half_rn(v.z), __float2half_rn(v.w)));
    } else if (bid < 32768) {                     // a2 cols 0..1023: q2_0 -> fp16
        int idx = (bid - 16384) * 256 + tid;
        int b = idx >> 8;
        int k4 = (idx & 255) << 2;
        float4 v = *(const float4*)(q2 + (size_t)b * 1024 + k4);
        size_t o = (size_t)b * 2048 + k4;
        *(uint2*)(g_a2 + o) = make_uint2(pk2h(__float2half_rn(v.x), __float2half_rn(v.y)),
                                         pk2h(__float2half_rn(v.z), __float2half_rn(v.w)));
    } else if (bid < 36864) {                     // w1 de-interleave -> [n][k]
        int idx = (bid - 32768) * 256 + tid;
        int n = idx >> 10, k = idx & 1023;
        int src = (k < 512) ? (2 * k) : (2 * (k - 512) + 1);
        g_w1[idx] = __float2half_rn(w1[(size_t)n * 1024 + src]);
    } else {                                      // w2|wsk combined -> [n][k]
        int idx = (bid - 36864) * 256 + tid;
        int n = idx / 3072, k = idx - n * 3072;
        float v;
        if (k < 1024)      v = w2 [(size_t)n * 2048 + 2 * k];
        else if (k < 2048) v = w2 [(size_t)n * 2048 + 2 * (k - 1024) + 1];
        else if (k < 2560) v = wsk[(size_t)n * 1024 + 2 * (k - 2048)];
        else               v = wsk[(size_t)n * 1024 + 2 * (k - 2560) + 1];
        g_w2[idx] = __float2half_rn(v);
    }
}

// ---------------------------------------------------------------------------
// Fused persistent GEMM kernel.
// Tiles 0..1023  : gemm1 (bm = (t>>3)*128, bn = (t&7)*128), K=1024
// Tiles 1024..1535: gemm2 (bm = (u>>2)*128, bn = (u&3)*128), K=3072
// CTA 128x128, K-chunk 64, 2-stage double buffer.
// 128 threads = 4 warps in a 2x2 grid, warp tile 64x64 (acc = 128 regs).
// pitch 144 B, 2 CTAs/SM, 255-reg budget.
// ---------------------------------------------------------------------------
#define PITCH      144
#define B_OFF      (128 * PITCH)
#define STAGE_B    (2 * 128 * PITCH)      // 36864
#define PARAM_OFF  (2 * STAGE_B)          // 73728
#define SMEM_TOTAL (PARAM_OFF + 2048)

__global__ __launch_bounds__(128, 2)
void fused_kernel(const float* __restrict__ b1, const float* __restrict__ s1,
                  const float* __restrict__ bb1, const float* __restrict__ m1,
                  const float* __restrict__ v1,
                  const float* __restrict__ b2, const float* __restrict__ bsk,
                  const float* __restrict__ s2, const float* __restrict__ bb2,
                  const float* __restrict__ m2, const float* __restrict__ v2,
                  float* __restrict__ outp)
{
    extern __shared__ char smem[];
    const uint32_t sbase = s2u(smem);
    const int tid  = threadIdx.x;
    const int wid  = tid >> 5, lane = tid & 31;
    const int wm   = (wid & 1) * 64;      // warp M offset
    const int wn   = (wid >> 1) * 64;     // warp N offset

    float* scp = (float*)(smem + PARAM_OFF);
    float* bip = scp + 128;
    float* bcp = scp + 256;
    int*  tilep = (int*)(smem + PARAM_OFF + 1536);

    const int mrow = lane & 15, msel = lane >> 4;
    const uint32_t aoff = (wm + mrow) * PITCH + msel * 16;
    const uint32_t boff = (wn + mrow) * PITCH + msel * 16;
    const int g  = lane >> 2, tg = lane & 3;

    for (;;) {
        if (tid == 0) *tilep = atomicAdd(&g_tile, 1);
        __syncthreads();
        const int t = *tilep;
        if (t >= 1536) break;

        const bool g1 = (t < 1024);
        int bm, bn, NC;
        if (g1) { bm = (t >> 3) * 128;          bn = (t & 7) * 128; NC = 16; }
        else    { int u = t - 1024; bm = (u >> 2) * 128; bn = (u & 3) * 128; NC = 48; }
        const __half* Bw = g1 ? g_w1 : g_w2;
        const int bstr   = g1 ? 1024 : 3072;

        if (!g1) {                        // wait for h1 rows [bm, bm+128)
            if (tid == 0) {
                const int* cp = &g_rowcnt[bm >> 7];
                while (ld_acq(cp) < 8) __nanosleep(128);
            }
            __syncthreads();
        }

        float acc[4][8][4];
#pragma unroll
        for (int i = 0; i < 4; i++)
#pragma unroll
            for (int j = 0; j < 8; j++)
#pragma unroll
                for (int k = 0; k < 4; k++) acc[i][j][k] = 0.f;

        auto load_stage = [&](int slot, int c) {
            const int k0 = c * 64;
            const __half* Aa; int astr, acol;
            if (g1)             { Aa = g_a1; astr = 1024; acol = k0; }
            else if (k0 < 2048) { Aa = g_a2; astr = 2048; acol = k0; }
            else                { Aa = g_a1; astr = 1024; acol = k0 - 2048; }
            const uint32_t st = sbase + slot * STAGE_B;
#pragma unroll
            for (int j = 0; j < 8; j++) {
                int idx = j * 128 + tid;
                int row = idx >> 3, ch = idx & 7;
                cp16(st + row * PITCH + ch * 16,
                     Aa + (size_t)(bm + row) * astr + acol + ch * 8);
                cp16(st + B_OFF + row * PITCH + ch * 16,
                     Bw + (size_t)(bn + row) * bstr + k0 + ch * 8);
            }
        };

        load_stage(0, 0); CP_COMMIT();

        for (int c = 0; c < NC; c++) {
            CP_WAIT(0);
            __syncthreads();
            if (c + 1 < NC) { load_stage((c + 1) & 1, c + 1); CP_COMMIT(); }
            const uint32_t st = sbase + (c & 1) * STAGE_B;
#pragma unroll
            for (int ks = 0; ks < 4; ks++) {           // four k16 substeps
                const uint32_t kadd = ks * 32;
                uint32_t fb[4][4];
#pragma unroll
                for (int p = 0; p < 4; p++)
                    ldmx4(fb[p], st + B_OFF + boff + p * 16 * PITCH + kadd);
#pragma unroll
                for (int mt = 0; mt < 4; mt++) {
                    uint32_t fa[4];
                    ldmx4(fa, st + aoff + mt * 16 * PITCH + kadd);
#pragma unroll
                    for (int nt = 0; nt < 8; nt++) {
                        const int p = nt >> 1, o = nt & 1;
                        mma16816(acc[mt][nt], fa, fb[p][o], fb[p][2 + o]);
                    }
                }
            }
        }

        // ---- epilogue: stage per-column params, then write ----
        {
            const int n = bn + tid;
            float s, bi, bc;
            if (g1) { s = s1[n] * rsqrtf(v1[n] + EPSV); bi = bb1[n] - m1[n] * s; bc = b1[n]; }
            else    { s = s2[n] * rsqrtf(v2[n] + EPSV); bi = bb2[n] - m2[n] * s; bc = b2[n] + bsk[n]; }
            scp[tid] = s; bip[tid] = bi; bcp[tid] = bc;
        }
        __syncthreads();

#pragma unroll
        for (int mt = 0; mt < 4; mt++) {
#pragma unroll
            for (int nt = 0; nt < 8; nt++) {
                const int nl = wn + nt * 8 + 2 * tg;
                const float s0 = scp[nl], s1v = scp[nl + 1];
                const float i0 = bip[nl], i1 = bip[nl + 1];
                const float c0 = bcp[nl], c1 = bcp[nl + 1];
#pragma unroll
                for (int half = 0; half < 2; half++) {
                    const int m = bm + wm + mt * 16 + g + half * 8;
                    const float v0 = fmaxf(acc[mt][nt][2 * half]     + c0, 0.f) * s0  + i0;
                    const float v1e = fmaxf(acc[mt][nt][2 * half + 1] + c1, 0.f) * s1v + i1;
                    if (g1) {
                        const size_t o = (size_t)m * 2048 + 1024 + bn + nl;
                        *(uint32_t*)(g_a2 + o) = pk2h(__float2half_rn(v0), __float2half_rn(v1e));
                    } else {
                        *(float2*)(outp + (size_t)m * 512 + bn + nl) = make_float2(v0, v1e);
                    }
                }
            }
        }

        if (g1) {               // publish h1 row-block completion
            __threadfence();
            __syncthreads();
            if (tid == 0) atomicAdd(&g_rowcnt[bm >> 7], 1);
        }
    }
}

// ---------------------------------------------------------------------------
extern "C" void kernel_launch(void* const* d_in, const int* in_sizes, int n_in,
                              void* d_out, int out_size) {
    const float* x   = (const float*)d_in[0];
    const float* q1  = (const float*)d_in[1];
    const float* q2  = (const float*)d_in[2];
    const float* w1  = (const float*)d_in[3];
    const float* b1  = (const float*)d_in[4];
    const float* w2  = (const float*)d_in[5];
    const float* b2  = (const float*)d_in[6];
    const float* wsk = (const float*)d_in[7];
    const float* bsk = (const float*)d_in[8];
    const float* s1  = (const float*)d_in[9];
    const float* bb1 = (const float*)d_in[10];
    const float* m1  = (const float*)d_in[11];
    const float* v1  = (const float*)d_in[12];
    const float* s2  = (const float*)d_in[13];
    const float* bb2 = (const float*)d_in[14];
    const float* m2  = (const float*)d_in[15];
    const float* v2  = (const float*)d_in[16];
    float* out = (float*)d_out;

    cudaFuncSetAttribute(fused_kernel, cudaFuncAttributeMaxDynamicSharedMemorySize, SMEM_TOTAL);

    // 16384 (a1) + 16384 (a2) + 4096 (w1) + 6144 (w2) blocks
    prep_kernel<<<43008, 256>>>(q1, x, q2, w1, w2, wsk);
    fused_kernel<<<296, 128, SMEM_TOTAL>>>(b1, s1, bb1, m1, v1,
                                           b2, bsk, s2, bb2, m2, v2, out);
}